// round 7
// baseline (speedup 1.0000x reference)
#include <cuda_runtime.h>
#include <cuda_fp16.h>
#include <cstdint>
#include <math.h>

#define BATCH   16384
#define TSTEPS  28
#define FEAT    28
#define HID     128
#define G3      384
#define NCLS    10

#define TILE_B  32
#define NTH     256
#define NKT     10          // K chunks of 16: kt 0..7 = h (k=j), kt 8,9 = x
#define NBLK    (BATCH / TILE_B)
#define NBFR    (8 * NKT * 4 * 2 * 32)

// B operand, fragment-linear, SPLIT hi/lo arrays:
// index [w(8)][kt(10)][g(4)][nt(2)][lane(32)] : uint2 {b0, b1}
__device__ __align__(16) uint2 gB_hi[NBFR];
__device__ __align__(16) uint2 gB_lo[NBFR];

__device__ __forceinline__ uint32_t pack_h2(float a, float b) {
    __half2 p = __floats2half2_rn(a, b);
    return *reinterpret_cast<uint32_t*>(&p);
}
__device__ __forceinline__ float2 unpack_h2(uint32_t u) {
    __half2 p = *reinterpret_cast<__half2*>(&u);
    return __half22float2(p);
}

__device__ __forceinline__ void mma16816(float* c, uint32_t a0, uint32_t a1,
                                         uint32_t a2, uint32_t a3,
                                         uint32_t b0, uint32_t b1) {
    asm volatile(
        "mma.sync.aligned.m16n8k16.row.col.f32.f16.f16.f32 "
        "{%0,%1,%2,%3}, {%4,%5,%6,%7}, {%8,%9}, {%0,%1,%2,%3};"
        : "+f"(c[0]), "+f"(c[1]), "+f"(c[2]), "+f"(c[3])
        : "r"(a0), "r"(a1), "r"(a2), "r"(a3), "r"(b0), "r"(b1));
}

__device__ __forceinline__ float sig_(float v) { return 1.0f / (1.0f + __expf(-v)); }
__device__ __forceinline__ float tanh_(float v) {
    float t = __expf(-2.0f * fabsf(v));
    float r = (1.0f - t) / (1.0f + t);
    return v < 0.0f ? -r : r;
}

// ---------------------------------------------------------------------------
// Prep: weights -> fragment-linear fp16 hi/lo (separate arrays).
// g: 0=z(col j), 1=r(col 128+j), 2=rh(col 256+j, R rows), 3=xh(col 256+j, W rows)
// ---------------------------------------------------------------------------
__global__ void prep_B(const float* __restrict__ Rk, const float* __restrict__ Wk) {
    int idx = blockIdx.x * blockDim.x + threadIdx.x;
    if (idx >= NBFR) return;
    int lane = idx & 31;
    int nt   = (idx >> 5) & 1;
    int g    = (idx >> 6) & 3;
    int kt   = (idx >> 8) % NKT;
    int w    = (idx >> 8) / NKT;
    int gid  = lane >> 2, tg = lane & 3;

    int jloc = 16 * w + 8 * nt + gid;
    int wcol = (g == 0) ? jloc : (g == 1 ? 128 + jloc : 256 + jloc);
    int k0   = kt * 16 + tg * 2;

    float v[4];
#pragma unroll
    for (int i = 0; i < 4; i++) {
        int k = k0 + (i >> 1) * 8 + (i & 1);
        float val = 0.0f;
        if (k < HID) { if (g != 3) val = Rk[k * G3 + wcol]; }
        else { int f = k - HID; if (f < FEAT && g != 2) val = Wk[f * G3 + wcol]; }
        v[i] = val;
    }
    __half h[4], l[4];
#pragma unroll
    for (int i = 0; i < 4; i++) {
        h[i] = __float2half_rn(v[i]);
        l[i] = __float2half_rn(v[i] - __half2float(h[i]));
    }
    uint2 fh, fl;
    fh.x = (uint32_t)(*(unsigned short*)&h[0]) | ((uint32_t)(*(unsigned short*)&h[1]) << 16);
    fh.y = (uint32_t)(*(unsigned short*)&h[2]) | ((uint32_t)(*(unsigned short*)&h[3]) << 16);
    fl.x = (uint32_t)(*(unsigned short*)&l[0]) | ((uint32_t)(*(unsigned short*)&l[1]) << 16);
    fl.y = (uint32_t)(*(unsigned short*)&l[2]) | ((uint32_t)(*(unsigned short*)&l[3]) << 16);
    gB_hi[idx] = fh;
    gB_lo[idx] = fl;
}

// ---------------------------------------------------------------------------
// Main fused GRU: persistent per-block scan, HMMA core.
// ---------------------------------------------------------------------------
__global__ void __launch_bounds__(NTH, 2)
gru_hmma_kernel(const float* __restrict__ x,
                const float* __restrict__ bias,
                const float* __restrict__ dw,
                const float* __restrict__ db,
                float* __restrict__ out)
{
    __shared__ uint4 Ah[2][NKT][2][32];
    __shared__ float hs[TILE_B][HID + 1];

    const int tid  = threadIdx.x;
    const int wid  = tid >> 5;
    const int lane = tid & 31;
    const int gid  = lane >> 2;
    const int tg   = lane & 3;
    const int b0   = blockIdx.x * TILE_B;
    const float* xg = x + (size_t)b0 * (TSTEPS * FEAT);

    for (int i = tid; i < 2 * NKT * 2 * 32; i += NTH)
        ((uint4*)Ah)[i] = make_uint4(0, 0, 0, 0);

    // bias -> accumulator-init registers: bp[u][e], u = g*2+nt
    float bp[8][2];
#pragma unroll
    for (int g = 0; g < 4; g++)
#pragma unroll
        for (int nt = 0; nt < 2; nt++) {
            int jl = 16 * wid + 8 * nt + 2 * tg;
#pragma unroll
            for (int e = 0; e < 2; e++) {
                int j = jl + e;
                float v;
                if      (g == 0) v = bias[j]       + bias[G3 + j];
                else if (g == 1) v = bias[128 + j] + bias[G3 + 128 + j];
                else if (g == 2) v = bias[G3 + 256 + j];
                else             v = bias[256 + j];
                bp[g * 2 + nt][e] = v;
            }
        }
    __syncthreads();

    auto stage_x = [&](int t) {
#pragma unroll
        for (int i = 0; i < 2; i++) {
            int s   = tid * 2 + i;
            int r   = s & 3;
            int ln  = (s >> 2) & 31;
            int mt  = (s >> 7) & 1;
            int kt8 = s >> 8;
            int gd = ln >> 2, tgg = ln & 3;
            int row = mt * 16 + gd + 8 * (r & 1);
            int kl  = kt8 * 16 + tgg * 2 + 8 * (r >> 1);
            float v0 = 0.0f, v1 = 0.0f;
            if (kl < FEAT) {
                const float* p = xg + (size_t)row * (TSTEPS * FEAT) + t * FEAT + kl;
                v0 = p[0];
                if (kl + 1 < FEAT) v1 = p[1];
            }
            __half h0 = __float2half_rn(v0), h1 = __float2half_rn(v1);
            float l0 = v0 - __half2float(h0), l1 = v1 - __half2float(h1);
            ((uint32_t*)&Ah[0][8 + kt8][mt][ln])[r] =
                (uint32_t)(*(unsigned short*)&h0) | ((uint32_t)(*(unsigned short*)&h1) << 16);
            ((uint32_t*)&Ah[1][8 + kt8][mt][ln])[r] = pack_h2(l0, l1);
        }
    };
    stage_x(0);
    __syncthreads();

    float acc[2][8][4];

    for (int t = 0; t < TSTEPS; t++) {
#pragma unroll
        for (int mt = 0; mt < 2; mt++)
#pragma unroll
            for (int u = 0; u < 8; u++) {
                acc[mt][u][0] = bp[u][0]; acc[mt][u][1] = bp[u][1];
                acc[mt][u][2] = bp[u][0]; acc[mt][u][3] = bp[u][1];
            }

        // ---- HMMA mainloop ----
#pragma unroll
        for (int kt = 0; kt < NKT; kt++) {
            uint4 Ah0 = Ah[0][kt][0][lane];
            uint4 Ah1 = Ah[0][kt][1][lane];
            uint4 Al0 = Ah[1][kt][0][lane];
            uint4 Al1 = Ah[1][kt][1][lane];
#pragma unroll
            for (int g = 0; g < 4; g++) {
                if (g == 2 && kt >= 8) continue;   // rh: h rows only
                if (g == 3 && kt <  8) continue;   // xh: x rows only
                const int base = (((wid * NKT + kt) * 4 + g) * 2) * 32 + lane;
                // B_hi: L1-resident (122 KB working set, fits); B_lo: L2-only (.cg)
                const uint2 Bh0 = __ldg(&gB_hi[base]);
                const uint2 Bh1 = __ldg(&gB_hi[base + 32]);
                const uint2 Bl0 = __ldcg(&gB_lo[base]);
                const uint2 Bl1 = __ldcg(&gB_lo[base + 32]);
                const int u0 = g * 2, u1 = g * 2 + 1;
                // B_hi consumers first (L1-fast), B_lo consumers last (hide L2 lat)
                mma16816(acc[0][u0], Ah0.x, Ah0.y, Ah0.z, Ah0.w, Bh0.x, Bh0.y); // hi*hi
                mma16816(acc[1][u0], Ah1.x, Ah1.y, Ah1.z, Ah1.w, Bh0.x, Bh0.y);
                mma16816(acc[0][u1], Ah0.x, Ah0.y, Ah0.z, Ah0.w, Bh1.x, Bh1.y);
                mma16816(acc[1][u1], Ah1.x, Ah1.y, Ah1.z, Ah1.w, Bh1.x, Bh1.y);
                mma16816(acc[0][u0], Al0.x, Al0.y, Al0.z, Al0.w, Bh0.x, Bh0.y); // lo*hi
                mma16816(acc[1][u0], Al1.x, Al1.y, Al1.z, Al1.w, Bh0.x, Bh0.y);
                mma16816(acc[0][u1], Al0.x, Al0.y, Al0.z, Al0.w, Bh1.x, Bh1.y);
                mma16816(acc[1][u1], Al1.x, Al1.y, Al1.z, Al1.w, Bh1.x, Bh1.y);
                mma16816(acc[0][u0], Ah0.x, Ah0.y, Ah0.z, Ah0.w, Bl0.x, Bl0.y); // hi*lo
                mma16816(acc[1][u0], Ah1.x, Ah1.y, Ah1.z, Ah1.w, Bl0.x, Bl0.y);
                mma16816(acc[0][u1], Ah0.x, Ah0.y, Ah0.z, Ah0.w, Bl1.x, Bl1.y);
                mma16816(acc[1][u1], Ah1.x, Ah1.y, Ah1.z, Ah1.w, Bl1.x, Bl1.y);
            }
        }
        __syncthreads();   // all warps done reading A frags

        // ---- epilogue: gates in-register; commit new h frags (kt = wid) ----
#pragma unroll
        for (int mt = 0; mt < 2; mt++) {
            uint4 Hh = Ah[0][wid][mt][lane];
            uint4 Hl = Ah[1][wid][mt][lane];
            const uint32_t hh_[4] = {Hh.x, Hh.y, Hh.z, Hh.w};
            const uint32_t hl_[4] = {Hl.x, Hl.y, Hl.z, Hl.w};
            uint32_t nh[4], nl[4];
#pragma unroll
            for (int r = 0; r < 4; r++) {
                const int nt = r >> 1;
                const int ci = (r & 1) * 2;
                float2 oh = unpack_h2(hh_[r]);
                float2 ol = unpack_h2(hl_[r]);
                float hold[2] = {oh.x + ol.x, oh.y + ol.y};
                float hnew[2];
#pragma unroll
                for (int e = 0; e < 2; e++) {
                    float z  = sig_(acc[mt][0 + nt][ci + e]);
                    float rr = sig_(acc[mt][2 + nt][ci + e]);
                    float hc = tanh_(acc[mt][6 + nt][ci + e] + rr * acc[mt][4 + nt][ci + e]);
                    hnew[e] = z * hold[e] + (1.0f - z) * hc;
                    if (t == TSTEPS - 1) {
                        int row = mt * 16 + gid + 8 * (r & 1);
                        int j   = 16 * wid + 8 * nt + 2 * tg + e;
                        hs[row][j] = hnew[e];
                    }
                }
                __half p0 = __float2half_rn(hnew[0]), p1 = __float2half_rn(hnew[1]);
                float r0 = hnew[0] - __half2float(p0), r1 = hnew[1] - __half2float(p1);
                nh[r] = (uint32_t)(*(unsigned short*)&p0) |
                        ((uint32_t)(*(unsigned short*)&p1) << 16);
                nl[r] = pack_h2(r0, r1);
            }
            Ah[0][wid][mt][lane] = make_uint4(nh[0], nh[1], nh[2], nh[3]);
            Ah[1][wid][mt][lane] = make_uint4(nl[0], nl[1], nl[2], nl[3]);
        }

        if (t < TSTEPS - 1) stage_x(t + 1);
        __syncthreads();   // new A frags visible to all warps
    }

    // ---- dense + softmax ----
    if (tid < TILE_B) {
        const int row = tid;
        float lg[NCLS];
#pragma unroll
        for (int c = 0; c < NCLS; c++) lg[c] = db[c];
        for (int j = 0; j < HID; j++) {
            float hv = hs[row][j];
#pragma unroll
            for (int c = 0; c < NCLS; c++) lg[c] = fmaf(hv, dw[j * NCLS + c], lg[c]);
        }
        float m = lg[0];
#pragma unroll
        for (int c = 1; c < NCLS; c++) m = fmaxf(m, lg[c]);
        float s = 0.0f;
#pragma unroll
        for (int c = 0; c < NCLS; c++) { lg[c] = expf(lg[c] - m); s += lg[c]; }
        float inv = 1.0f / s;
#pragma unroll
        for (int c = 0; c < NCLS; c++)
            out[(size_t)(b0 + row) * NCLS + c] = lg[c] * inv;
    }
}

extern "C" void kernel_launch(void* const* d_in, const int* in_sizes, int n_in,
                              void* d_out, int out_size) {
    const float* x    = (const float*)d_in[0];
    const float* Wk   = (const float*)d_in[1];
    const float* Rk   = (const float*)d_in[2];
    const float* bias = (const float*)d_in[3];
    const float* dw   = (const float*)d_in[4];
    const float* db   = (const float*)d_in[5];
    float* out = (float*)d_out;

    prep_B<<<(NBFR + 255) / 256, 256>>>(Rk, Wk);
    gru_hmma_kernel<<<NBLK, NTH>>>(x, bias, dw, db, out);
}